// round 15
// baseline (speedup 1.0000x reference)
#include <cuda_runtime.h>
#include <math.h>

#define BATCH   8
#define NA      8732
#define NAP     8736
#define NC      21
#define NFG     20
#define TOPK    200
#define PRE     1024
#define DCAP    1280
#define FBINS   2048
#define FSH     12
#define BASEB   0x3F000000u
#define CONF_T  0.5f
#define FULLM   0xFFFFFFFFu

// Exact midpoint for  div.rn.f32(inter,union) > 0.45f :
// 0.45f = 0x3EE66666 (even mantissa); ulp = 2^-25; midpoint = c + 2^-26.
// (double)inter and MID*(double)union are exact -> bit-identical decisions.
#define IOU_MID (0.449999988079071044921875 + 1.490116119384765625e-8)

// ---- scratch (static __device__, allocation-free) ----
__device__ float    g_clsT[BATCH * NFG * NAP];   // transposed scores; pad stays 0
__device__ float    g_kscore[BATCH * NFG * TOPK];
__device__ float4   g_kbox[BATCH * NFG * TOPK];
__device__ int      g_kcount[BATCH * NFG];
__device__ unsigned g_done[BATCH];               // wrap counters (stay 0 after run)

#define TR_TILE   128
#define TR_TPB    ((NA + TR_TILE - 1) / TR_TILE)   // 69
#define TR_BLOCKS (BATCH * TR_TPB)

// BIT-EXACT equivalent of the reference IoU test (R11 variant, measured best).
__device__ __forceinline__ bool iou_hit(float4 p, float pa, float4 q, float qa) {
    float w = fminf(p.z, q.z) - fmaxf(p.x, q.x) + 1.0f;
    float h = fminf(p.w, q.w) - fmaxf(p.y, q.y) + 1.0f;
    float inter = fmaxf(w, 0.0f) * fmaxf(h, 0.0f);
    float uni = pa + qa - inter;
    return (double)inter > IOU_MID * (double)uni;
}

// area exactly as stored in sar (same FP expression, deterministic)
__device__ __forceinline__ float box_area(float4 b) {
    return (b.z - b.x + 1.0f) * (b.w - b.y + 1.0f);
}

__device__ __forceinline__ unsigned finebin(unsigned bits) {
    unsigned fb = (bits - BASEB) >> FSH;
    return fb > (FBINS - 1u) ? (FBINS - 1u) : fb;
}

// Block suffix-scan over FBINS bins (512 threads, 4 consecutive bins each).
__device__ __forceinline__ int suffix_scan_2048(int* hist, int tid, int* sfx,
                                                int* above_out) {
    __shared__ int ws[16];
    __shared__ int s_total;
    const int lane = tid & 31, wid = tid >> 5;
    int b4 = tid * 4;
    int h0 = hist[b4], h1 = hist[b4 + 1], h2 = hist[b4 + 2], h3 = hist[b4 + 3];
    sfx[3] = h3; sfx[2] = h2 + sfx[3]; sfx[1] = h1 + sfx[2]; sfx[0] = h0 + sfx[1];
    int T = sfx[0], S = T;
#pragma unroll
    for (int off = 1; off < 32; off <<= 1) {
        int v = __shfl_down_sync(FULLM, S, off);
        if (lane + off < 32) S += v;
    }
    if (lane == 0) ws[wid] = S;
    __syncthreads();
    if (tid < 16) {
        int W = ws[tid];
#pragma unroll
        for (int off = 1; off < 16; off <<= 1) {
            int v = __shfl_down_sync(0x0000FFFFu, W, off);
            if (tid + off < 16) W += v;
        }
        ws[tid] = W;
        if (tid == 0) s_total = W;
    }
    __syncthreads();
    int above = ((wid < 15) ? ws[wid + 1] : 0) + (S - T);
    sfx[0] += above; sfx[1] += above; sfx[2] += above; sfx[3] += above;
    hist[b4]     = sfx[1];
    hist[b4 + 1] = sfx[2];
    hist[b4 + 2] = sfx[3];
    hist[b4 + 3] = above;
    *above_out = above;
    return s_total;
}

// ============================================================
// Kernel 1: transpose cls [b][a][c] -> g_clsT [b][c][a] (coalesced).
// ============================================================
__global__ void prep_kernel(const float* __restrict__ cls) {
    __shared__ float sh[TR_TILE * NC];
    int t = blockIdx.x;
    int b = t / TR_TPB, tile = t % TR_TPB;
    int a0 = tile * TR_TILE;
    int n = NA - a0; if (n > TR_TILE) n = TR_TILE;
    const float* src = cls + ((size_t)(b * NA + a0)) * NC;
    for (int i = threadIdx.x; i < n * NC; i += 256) sh[i] = src[i];
    __syncthreads();
    int half = threadIdx.x >> 7;
    int t2 = threadIdx.x & 127;
    if (t2 < n) {
        for (int c = half * 10; c < half * 10 + 10; ++c)
            g_clsT[((size_t)(b * NFG + c)) * NAP + a0 + t2] = sh[t2 * NC + c + 1];
    }
}

// ============================================================
// Kernel 2: bucket top-1024 + compacted fixpoint greedy NMS; last CTA
// per image also performs the per-image global top-200 (fused).
// ============================================================
__global__ __launch_bounds__(512, 2) void nms_kernel(const float* __restrict__ loc,
                                                     const float* __restrict__ anch,
                                                     float* __restrict__ out) {
    const int bc  = blockIdx.x;
    const int b   = bc / NFG;
    const int c20 = bc % NFG;
    const int tid = threadIdx.x;

    __shared__ __align__(16) int histbuf[FBINS];             // 8KB
    __shared__ __align__(16) unsigned long long dest[DCAP];  // 10KB
    __shared__ __align__(16) float4 sbox[PRE];               // 16KB
    __shared__ float  sar[PRE], ssc[PRE];                    // 8KB
    __shared__ short  cidx[256];                             // compacted->tile idx
    __shared__ unsigned kw[8], pf[8];
    __shared__ int psum[8];
    __shared__ int skc[NFG];
    __shared__ int s_fl[2];
    __shared__ int s_ftb, s_sel, s_last, s_ma;

    int* hist = histbuf;
    unsigned* colmask = (unsigned*)histbuf;
    float4* lbox = (float4*)dest;                            // kept boxes only

    for (int i = tid; i < FBINS; i += 512) hist[i] = 0;
    if (tid == 0) { s_ftb = -1; s_sel = 0; }
    __syncthreads();

    const float4* scol4 = reinterpret_cast<const float4*>(
        g_clsT + ((size_t)(b * NFG + c20)) * NAP);

    // ---- A: fine histogram, vectorized float4 (pad scores are 0) ----
    for (int v = tid; v < NAP / 4; v += 512) {
        float4 s4 = scol4[v];
        if (s4.x > CONF_T) atomicAdd(&hist[finebin(__float_as_uint(s4.x))], 1);
        if (s4.y > CONF_T) atomicAdd(&hist[finebin(__float_as_uint(s4.y))], 1);
        if (s4.z > CONF_T) atomicAdd(&hist[finebin(__float_as_uint(s4.z))], 1);
        if (s4.w > CONF_T) atomicAdd(&hist[finebin(__float_as_uint(s4.w))], 1);
    }
    __syncthreads();

    // ---- B: suffix scan; unique-boundary threshold (no atomics) ----
    int sfx[4], above;
    int total = suffix_scan_2048(hist, tid, sfx, &above);
    {
        int need = total < PRE ? total : PRE;
        if (need > 0) {
#pragma unroll
            for (int q = 0; q < 4; ++q) {
                int nxt = (q < 3) ? sfx[q + 1] : above;
                if (sfx[q] >= need && nxt < need) {
                    s_ftb = tid * 4 + q;
                    s_sel = sfx[q];
                }
            }
        }
    }
    __syncthreads();
    const int ftb = s_ftb;
    int count = s_sel; if (count > PRE) count = PRE; if (count > DCAP) count = DCAP;

    // ---- C: scatter to exact positions + per-bin tie sort ----
    if (ftb >= 0) {
        for (int v = tid; v < NAP / 4; v += 512) {
            float4 s4 = scol4[v];
            float sv[4] = {s4.x, s4.y, s4.z, s4.w};
#pragma unroll
            for (int k = 0; k < 4; ++k) {
                if (sv[k] > CONF_T) {
                    unsigned bits = __float_as_uint(sv[k]);
                    int fb = (int)finebin(bits);
                    if (fb >= ftb) {
                        int pos = atomicAdd(&hist[fb], 1);
                        if (pos < DCAP)
                            dest[pos] = ((unsigned long long)bits << 32) |
                                        (unsigned)(65535 - (4 * v + k));
                    }
                }
            }
        }
        __syncthreads();
        for (int fb = ftb + tid; fb < FBINS; fb += 512) {
            int lo = (fb == FBINS - 1) ? 0 : hist[fb + 1];
            int hi = hist[fb];
            if (hi > DCAP) hi = DCAP;
            if (lo > hi) lo = hi;
            for (int x = lo + 1; x < hi; ++x) {
                unsigned long long key = dest[x];
                int y = x - 1;
                while (y >= lo && dest[y] < key) { dest[y + 1] = dest[y]; --y; }
                dest[y + 1] = key;
            }
        }
        __syncthreads();
    }

    // ---- E: decode candidate boxes best-first ----
    const float4* loc4  = reinterpret_cast<const float4*>(loc);
    const float4* anch4 = reinterpret_cast<const float4*>(anch);
#pragma unroll
    for (int t = 0; t < 2; ++t) {
        int r = tid + t * 512;
        if (r < count) {
            unsigned long long key = dest[r];
            int a = 65535 - (int)(key & 0xFFFFu);
            float4 l  = loc4[b * NA + a];
            float4 an = anch4[a];
            float cx = an.x + l.x * 0.1f * an.z;
            float cy = an.y + l.y * 0.1f * an.w;
            float w  = an.z * expf(l.z * 0.2f);
            float h  = an.w * expf(l.w * 0.2f);
            float x1 = cx - w * 0.5f;
            float y1 = cy - h * 0.5f;
            float4 bb;
            bb.x = fminf(fmaxf(x1 * 300.0f, 0.0f), 299.0f);
            bb.y = fminf(fmaxf(y1 * 300.0f, 0.0f), 299.0f);
            bb.z = fminf(fmaxf((x1 + w) * 300.0f, 0.0f), 299.0f);
            bb.w = fminf(fmaxf((y1 + h) * 300.0f, 0.0f), 299.0f);
            sbox[r] = bb;
            sar[r] = box_area(bb);
            ssc[r] = __uint_as_float((unsigned)(key >> 32));
        }
    }
    __syncthreads();   // hist & dest dead; overlays live

    // ---- F: tiled greedy NMS: prefilter -> compact -> mask -> fixpoint ----
    int nL = 0;
    for (int base = 0; base < count && nL < TOPK; base += 256) {
        int m = count - base; if (m > 256) m = 256;
        if (tid < 8) pf[tid] = 0u;
        __syncthreads();
        // prefilter vs kept list: 4 candidates/thread (regs), 1/8 kept stream
        if (base > 0 && nL > 0) {
            int cg = (tid & 63) * 4;          // candidate group start
            int q  = tid >> 6;                // kept stream 0..7
            if (cg < m) {
                float4 cb0, cb1, cb2, cb3;
                float ca0 = 0.f, ca1 = 0.f, ca2 = 0.f, ca3 = 0.f;
                int nv = m - cg; if (nv > 4) nv = 4;
                cb0 = sbox[base + cg];           ca0 = sar[base + cg];
                cb1 = cb0; cb2 = cb0; cb3 = cb0;
                if (nv > 1) { cb1 = sbox[base + cg + 1]; ca1 = sar[base + cg + 1]; }
                if (nv > 2) { cb2 = sbox[base + cg + 2]; ca2 = sar[base + cg + 2]; }
                if (nv > 3) { cb3 = sbox[base + cg + 3]; ca3 = sar[base + cg + 3]; }
                bool d0 = false, d1 = false, d2 = false, d3 = false;
                for (int kk = q; kk < nL; kk += 8) {
                    float4 kb = lbox[kk];
                    float ka = box_area(kb);      // == old lar[kk], bit-exact
                    d0 |= iou_hit(kb, ka, cb0, ca0);
                    d1 |= iou_hit(kb, ka, cb1, ca1);
                    d2 |= iou_hit(kb, ka, cb2, ca2);
                    d3 |= iou_hit(kb, ka, cb3, ca3);
                }
                if (d0)           atomicOr(&pf[cg >> 5], 1u << (cg & 31));
                if (d1 && nv > 1) atomicOr(&pf[(cg + 1) >> 5], 1u << ((cg + 1) & 31));
                if (d2 && nv > 2) atomicOr(&pf[(cg + 2) >> 5], 1u << ((cg + 2) & 31));
                if (d3 && nv > 3) atomicOr(&pf[(cg + 3) >> 5], 1u << ((cg + 3) & 31));
            }
        }
        __syncthreads();
        // order-preserving compaction of alive candidates -> cidx[0..ma)
        if (tid < 8) {
            int lo = tid * 32;
            unsigned valid;
            if (m >= lo + 32)      valid = FULLM;
            else if (m <= lo)      valid = 0u;
            else                   valid = (1u << (m - lo)) - 1u;
            pf[tid] = valid & ~pf[tid];        // reuse pf as alive words
        }
        __syncthreads();
        if (tid < 8) {
            int s = 0;
            for (int w2 = 0; w2 < tid; ++w2) s += __popc(pf[w2]);
            psum[tid] = s;
            if (tid == 7) s_ma = s + __popc(pf[7]);
        }
        __syncthreads();
        const int ma = s_ma;
        if (ma > 0) {
            if (tid < m && ((pf[tid >> 5] >> (tid & 31)) & 1u)) {
                int r = psum[tid >> 5] +
                        __popc(pf[tid >> 5] & ((1u << (tid & 31)) - 1u));
                cidx[r] = (short)tid;
            }
            __syncthreads();
            // triangular IoU mask over COMPACTED indices.
            // One job/thread: 4 rows (regs) x one 32-col word; col loads
            // amortized over 4 rows; col area recomputed (no sar load).
            {
                const int words = (ma + 31) >> 5;
                int g = tid & 63, w = tid >> 6;      // 64 groups x 8 words
                int i0 = g * 4;
                if (i0 < ma && w < words) {
                    int nv = ma - i0; if (nv > 4) nv = 4;
                    float4 rb0, rb1, rb2, rb3;
                    float ra0 = 0.f, ra1 = 0.f, ra2 = 0.f, ra3 = 0.f;
                    rb0 = sbox[base + cidx[i0]];     ra0 = sar[base + cidx[i0]];
                    rb1 = rb0; rb2 = rb0; rb3 = rb0;
                    if (nv > 1) { rb1 = sbox[base + cidx[i0 + 1]]; ra1 = sar[base + cidx[i0 + 1]]; }
                    if (nv > 2) { rb2 = sbox[base + cidx[i0 + 2]]; ra2 = sar[base + cidx[i0 + 2]]; }
                    if (nv > 3) { rb3 = sbox[base + cidx[i0 + 3]]; ra3 = sar[base + cidx[i0 + 3]]; }
                    int j0 = w * 32;
                    // per-row column limits (j < i)
                    int jl0 = i0 - j0;     jl0 = jl0 < 0 ? 0 : (jl0 > 32 ? 32 : jl0);
                    int jl1 = i0 + 1 - j0; jl1 = jl1 < 0 ? 0 : (jl1 > 32 ? 32 : jl1);
                    int jl2 = i0 + 2 - j0; jl2 = jl2 < 0 ? 0 : (jl2 > 32 ? 32 : jl2);
                    int jl3 = i0 + 3 - j0; jl3 = jl3 < 0 ? 0 : (jl3 > 32 ? 32 : jl3);
                    if (nv < 4) jl3 = 0;
                    if (nv < 3) jl2 = 0;
                    if (nv < 2) jl1 = 0;
                    int jmax = jl0;
                    if (jl1 > jmax) jmax = jl1;
                    if (jl2 > jmax) jmax = jl2;
                    if (jl3 > jmax) jmax = jl3;
                    unsigned b0 = 0u, b1 = 0u, b2 = 0u, b3 = 0u;
                    for (int l = 0; l < jmax; ++l) {
                        float4 cb = sbox[base + cidx[j0 + l]];
                        float ca = box_area(cb);     // == sar, bit-exact
                        if (l < jl0 && iou_hit(rb0, ra0, cb, ca)) b0 |= 1u << l;
                        if (l < jl1 && iou_hit(rb1, ra1, cb, ca)) b1 |= 1u << l;
                        if (l < jl2 && iou_hit(rb2, ra2, cb, ca)) b2 |= 1u << l;
                        if (l < jl3 && iou_hit(rb3, ra3, cb, ca)) b3 |= 1u << l;
                    }
                    colmask[i0 * 8 + w] = b0;
                    if (nv > 1) colmask[(i0 + 1) * 8 + w] = b1;
                    if (nv > 2) colmask[(i0 + 2) * 8 + w] = b2;
                    if (nv > 3) colmask[(i0 + 3) * 8 + w] = b3;
                }
            }
            __syncthreads();
            if (tid < 8) {
                int lo = tid * 32;
                unsigned valid;
                if (ma >= lo + 32)      valid = FULLM;
                else if (ma <= lo)      valid = 0u;
                else                    valid = (1u << (ma - lo)) - 1u;
                kw[tid] = valid;
            }
            if (tid == 0) { s_fl[0] = 0; s_fl[1] = 0; }
            unsigned cm[8];
            int pre_ok = (tid < ma);
            __syncthreads();
            if (pre_ok) {
#pragma unroll
                for (int w = 0; w < 8; ++w) cm[w] = colmask[tid * 8 + w];
            }
            // fixpoint: 2 barriers per sweep, parity convergence flags
            int p = 0;
            for (;;) {
                int alive = 0;
                if (pre_ok) {
                    unsigned acc = (cm[0] & kw[0]) | (cm[1] & kw[1]) |
                                   (cm[2] & kw[2]) | (cm[3] & kw[3]) |
                                   (cm[4] & kw[4]) | (cm[5] & kw[5]) |
                                   (cm[6] & kw[6]) | (cm[7] & kw[7]);
                    alive = (acc == 0u);
                }
                __syncthreads();
                unsigned nw = __ballot_sync(FULLM, alive);
                if (tid < 256 && (tid & 31) == 0) {
                    if (nw != kw[tid >> 5]) s_fl[p] = 1;
                    kw[tid >> 5] = nw;
                }
                if (tid == 0) s_fl[p ^ 1] = 0;
                __syncthreads();
                if (!s_fl[p]) break;
                p ^= 1;
            }
            if (tid < 8) {
                int s = 0;
                for (int w2 = 0; w2 < tid; ++w2) s += __popc(kw[w2]);
                psum[tid] = s;
            }
            __syncthreads();
            int nk = psum[7] + __popc(kw[7]);
            int take = TOPK - nL; if (take > nk) take = nk;
            if (tid < ma && ((kw[tid >> 5] >> (tid & 31)) & 1u)) {
                int r = psum[tid >> 5] +
                        __popc(kw[tid >> 5] & ((1u << (tid & 31)) - 1u));
                if (r < take) {
                    int slot = nL + r;
                    int src = base + cidx[tid];
                    int gb = bc * TOPK + slot;
                    g_kscore[gb] = ssc[src];
                    g_kbox[gb]   = sbox[src];
                    lbox[slot]   = sbox[src];
                }
            }
            nL += take;
        }
        __syncthreads();
    }
    if (tid == 0) g_kcount[bc] = nL;

    // ---- G: completion counter; last CTA of image runs the global top-200 ----
    if (tid == 0) {
        __threadfence();
        unsigned old = atomicInc(&g_done[b], NFG - 1);
        s_last = (old == NFG - 1);
    }
    __syncthreads();
    if (!s_last) return;
    __threadfence();

    // ---- H: per-image global top-200 (bucket) ----
    for (int i = tid; i < FBINS; i += 512) hist[i] = 0;
    if (tid == 0) { s_ftb = -1; s_sel = 0; }
    if (tid < NFG) skc[tid] = g_kcount[b * NFG + tid];
    __syncthreads();

    for (int idx = tid; idx < NFG * TOPK; idx += 512) {
        int c = idx / TOPK, slot = idx - c * TOPK;
        if (slot < skc[c]) {
            unsigned bits = __float_as_uint(g_kscore[(b * NFG + c) * TOPK + slot]);
            atomicAdd(&hist[finebin(bits)], 1);
        }
    }
    __syncthreads();

    int total2 = suffix_scan_2048(hist, tid, sfx, &above);
    {
        int need = total2 < TOPK ? total2 : TOPK;
        if (need > 0) {
#pragma unroll
            for (int q = 0; q < 4; ++q) {
                int nxt = (q < 3) ? sfx[q + 1] : above;
                if (sfx[q] >= need && nxt < need) {
                    s_ftb = tid * 4 + q;
                    s_sel = sfx[q];
                }
            }
        }
    }
    __syncthreads();
    const int ftb2 = s_ftb;
    int count2 = s_sel; if (count2 > TOPK) count2 = TOPK; if (count2 > 512) count2 = 512;

    if (ftb2 >= 0) {
        for (int idx = tid; idx < NFG * TOPK; idx += 512) {
            int c = idx / TOPK, slot = idx - c * TOPK;
            if (slot < skc[c]) {
                unsigned bits = __float_as_uint(g_kscore[(b * NFG + c) * TOPK + slot]);
                int fb = (int)finebin(bits);
                if (fb >= ftb2) {
                    int pos = atomicAdd(&hist[fb], 1);
                    if (pos < 512)
                        dest[pos] = ((unsigned long long)bits << 32) |
                                    (0xFFFFFFFFu - (unsigned)(c * 256 + slot));
                }
            }
        }
        __syncthreads();
        for (int fb = ftb2 + tid; fb < FBINS; fb += 512) {
            int lo = (fb == FBINS - 1) ? 0 : hist[fb + 1];
            int hi = hist[fb];
            if (hi > 512) hi = 512;
            if (lo > hi) lo = hi;
            for (int x = lo + 1; x < hi; ++x) {
                unsigned long long key = dest[x];
                int y = x - 1;
                while (y >= lo && dest[y] < key) { dest[y + 1] = dest[y]; --y; }
                dest[y + 1] = key;
            }
        }
        __syncthreads();
    }

    if (tid < TOPK) {
        float b0 = 0.f, b1 = 0.f, b2 = 0.f, b3 = 0.f, sco = 0.f, lab = 0.f;
        if (tid < count2) {
            unsigned long long key = dest[tid];
            unsigned code = 0xFFFFFFFFu - (unsigned)(key & 0xFFFFFFFFu);
            int c    = (int)(code >> 8);
            int slot = (int)(code & 255u);
            float4 kb = g_kbox[(b * NFG + c) * TOPK + slot];
            sco = __uint_as_float((unsigned)(key >> 32));
            b0 = kb.x; b1 = kb.y; b2 = kb.z; b3 = kb.w;
            lab = (float)(c + 1);
        }
        out[(b * TOPK + tid) * 4 + 0] = b0;
        out[(b * TOPK + tid) * 4 + 1] = b1;
        out[(b * TOPK + tid) * 4 + 2] = b2;
        out[(b * TOPK + tid) * 4 + 3] = b3;
        out[BATCH * TOPK * 4 + b * TOPK + tid] = sco;
        out[BATCH * TOPK * 5 + b * TOPK + tid] = lab;
    }
}

// ============================================================
extern "C" void kernel_launch(void* const* d_in, const int* in_sizes, int n_in,
                              void* d_out, int out_size) {
    const float* cls  = (const float*)d_in[0];  // [8, 8732, 21]
    const float* loc  = (const float*)d_in[1];  // [8, 8732, 4]
    const float* anch = (const float*)d_in[2];  // [8732, 4]
    float* out = (float*)d_out;

    prep_kernel<<<TR_BLOCKS, 256>>>(cls);
    nms_kernel<<<BATCH * NFG, 512>>>(loc, anch, out);
}

// round 16
// speedup vs baseline: 1.1130x; 1.1130x over previous
#include <cuda_runtime.h>
#include <math.h>

#define BATCH   8
#define NA      8732
#define NAP     8736
#define NC      21
#define NFG     20
#define TOPK    200
#define PRE     1024
#define DCAP    1280
#define FBINS   2048
#define FSH     12
#define BASEB   0x3F000000u
#define CONF_T  0.5f
#define FULLM   0xFFFFFFFFu

// Exact midpoint for  div.rn.f32(inter,union) > 0.45f :
// 0.45f = 0x3EE66666 (even mantissa); ulp = 2^-25; midpoint = c + 2^-26.
// (double)inter and MID*(double)union are exact -> bit-identical decisions.
#define IOU_MID (0.449999988079071044921875 + 1.490116119384765625e-8)

// ---- scratch (static __device__, allocation-free) ----
__device__ float    g_clsT[BATCH * NFG * NAP];   // transposed scores; pad stays 0
__device__ float    g_kscore[BATCH * NFG * TOPK];
__device__ float4   g_kbox[BATCH * NFG * TOPK];
__device__ int      g_kcount[BATCH * NFG];
__device__ unsigned g_done[BATCH];               // wrap counters (stay 0 after run)

#define TR_TILE   128
#define TR_TPB    ((NA + TR_TILE - 1) / TR_TILE)   // 69
#define TR_BLOCKS (BATCH * TR_TPB)

// BIT-EXACT equivalent of the reference IoU test (R11 variant, measured best).
__device__ __forceinline__ bool iou_hit(float4 p, float pa, float4 q, float qa) {
    float w = fminf(p.z, q.z) - fmaxf(p.x, q.x) + 1.0f;
    float h = fminf(p.w, q.w) - fmaxf(p.y, q.y) + 1.0f;
    float inter = fmaxf(w, 0.0f) * fmaxf(h, 0.0f);
    float uni = pa + qa - inter;
    return (double)inter > IOU_MID * (double)uni;
}

__device__ __forceinline__ unsigned finebin(unsigned bits) {
    unsigned fb = (bits - BASEB) >> FSH;
    return fb > (FBINS - 1u) ? (FBINS - 1u) : fb;
}

// Block suffix-scan over FBINS bins (512 threads, 4 consecutive bins each).
__device__ __forceinline__ int suffix_scan_2048(int* hist, int tid, int* sfx,
                                                int* above_out) {
    __shared__ int ws[16];
    __shared__ int s_total;
    const int lane = tid & 31, wid = tid >> 5;
    int b4 = tid * 4;
    int h0 = hist[b4], h1 = hist[b4 + 1], h2 = hist[b4 + 2], h3 = hist[b4 + 3];
    sfx[3] = h3; sfx[2] = h2 + sfx[3]; sfx[1] = h1 + sfx[2]; sfx[0] = h0 + sfx[1];
    int T = sfx[0], S = T;
#pragma unroll
    for (int off = 1; off < 32; off <<= 1) {
        int v = __shfl_down_sync(FULLM, S, off);
        if (lane + off < 32) S += v;
    }
    if (lane == 0) ws[wid] = S;
    __syncthreads();
    if (tid < 16) {
        int W = ws[tid];
#pragma unroll
        for (int off = 1; off < 16; off <<= 1) {
            int v = __shfl_down_sync(0x0000FFFFu, W, off);
            if (tid + off < 16) W += v;
        }
        ws[tid] = W;
        if (tid == 0) s_total = W;
    }
    __syncthreads();
    int above = ((wid < 15) ? ws[wid + 1] : 0) + (S - T);
    sfx[0] += above; sfx[1] += above; sfx[2] += above; sfx[3] += above;
    hist[b4]     = sfx[1];
    hist[b4 + 1] = sfx[2];
    hist[b4 + 2] = sfx[3];
    hist[b4 + 3] = above;
    *above_out = above;
    return s_total;
}

// ============================================================
// Kernel 1: transpose cls [b][a][c] -> g_clsT [b][c][a] (coalesced).
// ============================================================
__global__ void prep_kernel(const float* __restrict__ cls) {
    __shared__ float sh[TR_TILE * NC];
    int t = blockIdx.x;
    int b = t / TR_TPB, tile = t % TR_TPB;
    int a0 = tile * TR_TILE;
    int n = NA - a0; if (n > TR_TILE) n = TR_TILE;
    const float* src = cls + ((size_t)(b * NA + a0)) * NC;
    for (int i = threadIdx.x; i < n * NC; i += 256) sh[i] = src[i];
    __syncthreads();
    int half = threadIdx.x >> 7;
    int t2 = threadIdx.x & 127;
    if (t2 < n) {
        for (int c = half * 10; c < half * 10 + 10; ++c)
            g_clsT[((size_t)(b * NFG + c)) * NAP + a0 + t2] = sh[t2 * NC + c + 1];
    }
}

// ============================================================
// Kernel 2: bucket top-1024 + compacted fixpoint greedy NMS; last CTA
// per image also performs the per-image global top-200 (fused).
// ============================================================
__global__ __launch_bounds__(512, 2) void nms_kernel(const float* __restrict__ loc,
                                                     const float* __restrict__ anch,
                                                     float* __restrict__ out) {
    const int bc  = blockIdx.x;
    const int b   = bc / NFG;
    const int c20 = bc % NFG;
    const int tid = threadIdx.x;

    __shared__ __align__(16) int histbuf[FBINS];             // 8KB
    __shared__ __align__(16) unsigned long long dest[DCAP];  // 10KB
    __shared__ __align__(16) float4 sbox[PRE];               // 16KB
    __shared__ float  sar[PRE], ssc[PRE];                    // 8KB
    __shared__ short  cidx[256];                             // compacted->tile idx
    __shared__ unsigned kw[8], pf[8];
    __shared__ int psum[8];
    __shared__ int skc[NFG];
    __shared__ int s_fl[2];
    __shared__ int s_ftb, s_sel, s_last, s_ma;

    int* hist = histbuf;
    unsigned* colmask = (unsigned*)histbuf;
    float4* lbox = (float4*)dest;
    float*  lar  = (float*)(dest + 512);

    for (int i = tid; i < FBINS; i += 512) hist[i] = 0;
    if (tid == 0) { s_ftb = -1; s_sel = 0; }
    __syncthreads();

    const float4* scol4 = reinterpret_cast<const float4*>(
        g_clsT + ((size_t)(b * NFG + c20)) * NAP);

    // ---- A: fine histogram, vectorized float4 (pad scores are 0) ----
    for (int v = tid; v < NAP / 4; v += 512) {
        float4 s4 = scol4[v];
        if (s4.x > CONF_T) atomicAdd(&hist[finebin(__float_as_uint(s4.x))], 1);
        if (s4.y > CONF_T) atomicAdd(&hist[finebin(__float_as_uint(s4.y))], 1);
        if (s4.z > CONF_T) atomicAdd(&hist[finebin(__float_as_uint(s4.z))], 1);
        if (s4.w > CONF_T) atomicAdd(&hist[finebin(__float_as_uint(s4.w))], 1);
    }
    __syncthreads();

    // ---- B: suffix scan; unique-boundary threshold (no atomics) ----
    int sfx[4], above;
    int total = suffix_scan_2048(hist, tid, sfx, &above);
    {
        int need = total < PRE ? total : PRE;
        if (need > 0) {
#pragma unroll
            for (int q = 0; q < 4; ++q) {
                int nxt = (q < 3) ? sfx[q + 1] : above;
                if (sfx[q] >= need && nxt < need) {
                    s_ftb = tid * 4 + q;
                    s_sel = sfx[q];
                }
            }
        }
    }
    __syncthreads();
    const int ftb = s_ftb;
    int count = s_sel; if (count > PRE) count = PRE; if (count > DCAP) count = DCAP;

    // ---- C: scatter to exact positions + per-bin tie sort ----
    if (ftb >= 0) {
        for (int v = tid; v < NAP / 4; v += 512) {
            float4 s4 = scol4[v];
            float sv[4] = {s4.x, s4.y, s4.z, s4.w};
#pragma unroll
            for (int k = 0; k < 4; ++k) {
                if (sv[k] > CONF_T) {
                    unsigned bits = __float_as_uint(sv[k]);
                    int fb = (int)finebin(bits);
                    if (fb >= ftb) {
                        int pos = atomicAdd(&hist[fb], 1);
                        if (pos < DCAP)
                            dest[pos] = ((unsigned long long)bits << 32) |
                                        (unsigned)(65535 - (4 * v + k));
                    }
                }
            }
        }
        __syncthreads();
        for (int fb = ftb + tid; fb < FBINS; fb += 512) {
            int lo = (fb == FBINS - 1) ? 0 : hist[fb + 1];
            int hi = hist[fb];
            if (hi > DCAP) hi = DCAP;
            if (lo > hi) lo = hi;
            for (int x = lo + 1; x < hi; ++x) {
                unsigned long long key = dest[x];
                int y = x - 1;
                while (y >= lo && dest[y] < key) { dest[y + 1] = dest[y]; --y; }
                dest[y + 1] = key;
            }
        }
        __syncthreads();
    }

    // ---- E: decode candidate boxes best-first ----
    const float4* loc4  = reinterpret_cast<const float4*>(loc);
    const float4* anch4 = reinterpret_cast<const float4*>(anch);
#pragma unroll
    for (int t = 0; t < 2; ++t) {
        int r = tid + t * 512;
        if (r < count) {
            unsigned long long key = dest[r];
            int a = 65535 - (int)(key & 0xFFFFu);
            float4 l  = loc4[b * NA + a];
            float4 an = anch4[a];
            float cx = an.x + l.x * 0.1f * an.z;
            float cy = an.y + l.y * 0.1f * an.w;
            float w  = an.z * expf(l.z * 0.2f);
            float h  = an.w * expf(l.w * 0.2f);
            float x1 = cx - w * 0.5f;
            float y1 = cy - h * 0.5f;
            float4 bb;
            bb.x = fminf(fmaxf(x1 * 300.0f, 0.0f), 299.0f);
            bb.y = fminf(fmaxf(y1 * 300.0f, 0.0f), 299.0f);
            bb.z = fminf(fmaxf((x1 + w) * 300.0f, 0.0f), 299.0f);
            bb.w = fminf(fmaxf((y1 + h) * 300.0f, 0.0f), 299.0f);
            sbox[r] = bb;
            sar[r] = (bb.z - bb.x + 1.0f) * (bb.w - bb.y + 1.0f);
            ssc[r] = __uint_as_float((unsigned)(key >> 32));
        }
    }
    __syncthreads();   // hist & dest dead; overlays live

    // ---- F: tiled greedy NMS: prefilter -> compact -> mask -> fixpoint ----
    int nL = 0;
    for (int base = 0; base < count && nL < TOPK; base += 256) {
        int m = count - base; if (m > 256) m = 256;
        if (tid < 8) pf[tid] = 0u;
        __syncthreads();
        // prefilter vs kept list: 2 threads per candidate, 4-wide batched
        if (base > 0 && nL > 0) {
            int i = tid >> 1, half = tid & 1;
            if (i < m) {
                float4 bb = sbox[base + i];
                float ab = sar[base + i];
                bool dead = false;
                int k = half;
                for (; k + 6 < nL; k += 8) {
                    dead |= iou_hit(lbox[k],     lar[k],     bb, ab);
                    dead |= iou_hit(lbox[k + 2], lar[k + 2], bb, ab);
                    dead |= iou_hit(lbox[k + 4], lar[k + 4], bb, ab);
                    dead |= iou_hit(lbox[k + 6], lar[k + 6], bb, ab);
                }
                for (; k < nL; k += 2)
                    dead |= iou_hit(lbox[k], lar[k], bb, ab);
                if (dead) atomicOr(&pf[i >> 5], 1u << (i & 31));
            }
        }
        __syncthreads();
        // order-preserving compaction of alive candidates -> cidx[0..ma)
        if (tid < 8) {
            int lo = tid * 32;
            unsigned valid;
            if (m >= lo + 32)      valid = FULLM;
            else if (m <= lo)      valid = 0u;
            else                   valid = (1u << (m - lo)) - 1u;
            pf[tid] = valid & ~pf[tid];        // reuse pf as alive words
        }
        __syncthreads();
        if (tid < 8) {
            int s = 0;
            for (int w2 = 0; w2 < tid; ++w2) s += __popc(pf[w2]);
            psum[tid] = s;
            if (tid == 7) s_ma = s + __popc(pf[7]);
        }
        __syncthreads();
        const int ma = s_ma;
        if (ma > 0) {
            if (tid < m && ((pf[tid >> 5] >> (tid & 31)) & 1u)) {
                int r = psum[tid >> 5] +
                        __popc(pf[tid >> 5] & ((1u << (tid & 31)) - 1u));
                cidx[r] = (short)tid;
            }
            __syncthreads();
            const int words = (ma + 31) >> 5;
            if (ma == m) {
                // identity compaction: direct indexing, no cidx loads
#pragma unroll
                for (int q = 0; q < 4; ++q) {
                    int jid = tid + q * 512;
                    int i = jid & 255, w = jid >> 8;
                    int jn = i - w * 32; if (jn > 32) jn = 32;
                    if (i < ma && w < words) {
                        if (jn > 0) {
                            float4 bi = sbox[base + i];
                            float ai = sar[base + i];
                            unsigned bits = 0u;
                            int j0 = base + w * 32;
                            int l = 0;
                            for (; l + 4 <= jn; l += 4) {
                                if (iou_hit(bi, ai, sbox[j0 + l],     sar[j0 + l]))     bits |= 1u << l;
                                if (iou_hit(bi, ai, sbox[j0 + l + 1], sar[j0 + l + 1])) bits |= 1u << (l + 1);
                                if (iou_hit(bi, ai, sbox[j0 + l + 2], sar[j0 + l + 2])) bits |= 1u << (l + 2);
                                if (iou_hit(bi, ai, sbox[j0 + l + 3], sar[j0 + l + 3])) bits |= 1u << (l + 3);
                            }
                            for (; l < jn; ++l)
                                if (iou_hit(bi, ai, sbox[j0 + l], sar[j0 + l]))
                                    bits |= 1u << l;
                            colmask[i * 8 + w] = bits;
                        } else {
                            colmask[i * 8 + w] = 0u;
                        }
                    }
                }
            } else {
                // general: compacted indices
#pragma unroll
                for (int q = 0; q < 4; ++q) {
                    int jid = tid + q * 512;
                    int i = jid & 255, w = jid >> 8;
                    int jn = i - w * 32; if (jn > 32) jn = 32;
                    if (i < ma && w < words) {
                        if (jn > 0) {
                            int ti = base + cidx[i];
                            float4 bi = sbox[ti];
                            float ai = sar[ti];
                            unsigned bits = 0u;
                            int j0 = w * 32;
                            int l = 0;
                            for (; l + 4 <= jn; l += 4) {
                                int a0 = base + cidx[j0 + l];
                                int a1 = base + cidx[j0 + l + 1];
                                int a2 = base + cidx[j0 + l + 2];
                                int a3 = base + cidx[j0 + l + 3];
                                if (iou_hit(bi, ai, sbox[a0], sar[a0])) bits |= 1u << l;
                                if (iou_hit(bi, ai, sbox[a1], sar[a1])) bits |= 1u << (l + 1);
                                if (iou_hit(bi, ai, sbox[a2], sar[a2])) bits |= 1u << (l + 2);
                                if (iou_hit(bi, ai, sbox[a3], sar[a3])) bits |= 1u << (l + 3);
                            }
                            for (; l < jn; ++l) {
                                int aj = base + cidx[j0 + l];
                                if (iou_hit(bi, ai, sbox[aj], sar[aj]))
                                    bits |= 1u << l;
                            }
                            colmask[i * 8 + w] = bits;
                        } else {
                            colmask[i * 8 + w] = 0u;
                        }
                    }
                }
            }
            __syncthreads();
            if (tid < 8) {
                int lo = tid * 32;
                unsigned valid;
                if (ma >= lo + 32)      valid = FULLM;
                else if (ma <= lo)      valid = 0u;
                else                    valid = (1u << (ma - lo)) - 1u;
                kw[tid] = valid;
            }
            if (tid == 0) { s_fl[0] = 0; s_fl[1] = 0; }
            unsigned cm[8];
            int pre_ok = (tid < ma);
            __syncthreads();
            if (pre_ok) {
#pragma unroll
                for (int w = 0; w < 8; ++w) cm[w] = colmask[tid * 8 + w];
            }
            // fixpoint: 2 barriers per sweep, parity convergence flags
            int p = 0;
            for (;;) {
                int alive = 0;
                if (pre_ok) {
                    unsigned acc = (cm[0] & kw[0]) | (cm[1] & kw[1]) |
                                   (cm[2] & kw[2]) | (cm[3] & kw[3]) |
                                   (cm[4] & kw[4]) | (cm[5] & kw[5]) |
                                   (cm[6] & kw[6]) | (cm[7] & kw[7]);
                    alive = (acc == 0u);
                }
                __syncthreads();
                unsigned nw = __ballot_sync(FULLM, alive);
                if (tid < 256 && (tid & 31) == 0) {
                    if (nw != kw[tid >> 5]) s_fl[p] = 1;
                    kw[tid >> 5] = nw;
                }
                if (tid == 0) s_fl[p ^ 1] = 0;
                __syncthreads();
                if (!s_fl[p]) break;
                p ^= 1;
            }
            if (tid < 8) {
                int s = 0;
                for (int w2 = 0; w2 < tid; ++w2) s += __popc(kw[w2]);
                psum[tid] = s;
            }
            __syncthreads();
            int nk = psum[7] + __popc(kw[7]);
            int take = TOPK - nL; if (take > nk) take = nk;
            if (tid < ma && ((kw[tid >> 5] >> (tid & 31)) & 1u)) {
                int r = psum[tid >> 5] +
                        __popc(kw[tid >> 5] & ((1u << (tid & 31)) - 1u));
                if (r < take) {
                    int slot = nL + r;
                    int src = base + cidx[tid];
                    int gb = bc * TOPK + slot;
                    g_kscore[gb] = ssc[src];
                    g_kbox[gb]   = sbox[src];
                    lbox[slot]   = sbox[src];
                    lar[slot]    = sar[src];
                }
            }
            nL += take;
        }
        __syncthreads();
    }
    if (tid == 0) g_kcount[bc] = nL;

    // ---- G: completion counter; last CTA of image runs the global top-200 ----
    if (tid == 0) {
        __threadfence();
        unsigned old = atomicInc(&g_done[b], NFG - 1);
        s_last = (old == NFG - 1);
    }
    __syncthreads();
    if (!s_last) return;
    __threadfence();

    // ---- H: per-image global top-200 (bucket) ----
    for (int i = tid; i < FBINS; i += 512) hist[i] = 0;
    if (tid == 0) { s_ftb = -1; s_sel = 0; }
    if (tid < NFG) skc[tid] = g_kcount[b * NFG + tid];
    __syncthreads();

    for (int idx = tid; idx < NFG * TOPK; idx += 512) {
        int c = idx / TOPK, slot = idx - c * TOPK;
        if (slot < skc[c]) {
            unsigned bits = __float_as_uint(g_kscore[(b * NFG + c) * TOPK + slot]);
            atomicAdd(&hist[finebin(bits)], 1);
        }
    }
    __syncthreads();

    int total2 = suffix_scan_2048(hist, tid, sfx, &above);
    {
        int need = total2 < TOPK ? total2 : TOPK;
        if (need > 0) {
#pragma unroll
            for (int q = 0; q < 4; ++q) {
                int nxt = (q < 3) ? sfx[q + 1] : above;
                if (sfx[q] >= need && nxt < need) {
                    s_ftb = tid * 4 + q;
                    s_sel = sfx[q];
                }
            }
        }
    }
    __syncthreads();
    const int ftb2 = s_ftb;
    int count2 = s_sel; if (count2 > TOPK) count2 = TOPK; if (count2 > 512) count2 = 512;

    if (ftb2 >= 0) {
        for (int idx = tid; idx < NFG * TOPK; idx += 512) {
            int c = idx / TOPK, slot = idx - c * TOPK;
            if (slot < skc[c]) {
                unsigned bits = __float_as_uint(g_kscore[(b * NFG + c) * TOPK + slot]);
                int fb = (int)finebin(bits);
                if (fb >= ftb2) {
                    int pos = atomicAdd(&hist[fb], 1);
                    if (pos < 512)
                        dest[pos] = ((unsigned long long)bits << 32) |
                                    (0xFFFFFFFFu - (unsigned)(c * 256 + slot));
                }
            }
        }
        __syncthreads();
        for (int fb = ftb2 + tid; fb < FBINS; fb += 512) {
            int lo = (fb == FBINS - 1) ? 0 : hist[fb + 1];
            int hi = hist[fb];
            if (hi > 512) hi = 512;
            if (lo > hi) lo = hi;
            for (int x = lo + 1; x < hi; ++x) {
                unsigned long long key = dest[x];
                int y = x - 1;
                while (y >= lo && dest[y] < key) { dest[y + 1] = dest[y]; --y; }
                dest[y + 1] = key;
            }
        }
        __syncthreads();
    }

    if (tid < TOPK) {
        float b0 = 0.f, b1 = 0.f, b2 = 0.f, b3 = 0.f, sco = 0.f, lab = 0.f;
        if (tid < count2) {
            unsigned long long key = dest[tid];
            unsigned code = 0xFFFFFFFFu - (unsigned)(key & 0xFFFFFFFFu);
            int c    = (int)(code >> 8);
            int slot = (int)(code & 255u);
            float4 kb = g_kbox[(b * NFG + c) * TOPK + slot];
            sco = __uint_as_float((unsigned)(key >> 32));
            b0 = kb.x; b1 = kb.y; b2 = kb.z; b3 = kb.w;
            lab = (float)(c + 1);
        }
        out[(b * TOPK + tid) * 4 + 0] = b0;
        out[(b * TOPK + tid) * 4 + 1] = b1;
        out[(b * TOPK + tid) * 4 + 2] = b2;
        out[(b * TOPK + tid) * 4 + 3] = b3;
        out[BATCH * TOPK * 4 + b * TOPK + tid] = sco;
        out[BATCH * TOPK * 5 + b * TOPK + tid] = lab;
    }
}

// ============================================================
extern "C" void kernel_launch(void* const* d_in, const int* in_sizes, int n_in,
                              void* d_out, int out_size) {
    const float* cls  = (const float*)d_in[0];  // [8, 8732, 21]
    const float* loc  = (const float*)d_in[1];  // [8, 8732, 4]
    const float* anch = (const float*)d_in[2];  // [8732, 4]
    float* out = (float*)d_out;

    prep_kernel<<<TR_BLOCKS, 256>>>(cls);
    nms_kernel<<<BATCH * NFG, 512>>>(loc, anch, out);
}

// round 17
// speedup vs baseline: 1.3049x; 1.1724x over previous
#include <cuda_runtime.h>
#include <math.h>

#define BATCH   8
#define NA      8732
#define NAP     8736
#define NC      21
#define NFG     20
#define TOPK    200
#define PRE     1024
#define DCAP    1280
#define FBINS   2048
#define FSH     12
#define BASEB   0x3F000000u
#define CONF_T  0.5f
#define FULLM   0xFFFFFFFFu

// Exact midpoint for  div.rn.f32(inter,union) > 0.45f :
// 0.45f = 0x3EE66666 (even mantissa); ulp = 2^-25; midpoint = c + 2^-26.
// (double)inter and MID*(double)union are exact -> bit-identical decisions.
#define IOU_MID (0.449999988079071044921875 + 1.490116119384765625e-8)

// ---- scratch (static __device__, allocation-free) ----
__device__ float    g_clsT[BATCH * NFG * NAP];   // transposed scores; pad stays 0
__device__ float4   g_cbox[BATCH * NFG * PRE];   // decoded candidates (cold path)
__device__ float    g_cscore[BATCH * NFG * PRE];
__device__ int      g_ccount[BATCH * NFG];
__device__ float    g_kscore[BATCH * NFG * TOPK];
__device__ float4   g_kbox[BATCH * NFG * TOPK];
__device__ int      g_kcount[BATCH * NFG];
__device__ unsigned g_done[BATCH];               // wrap counters (stay 0 after run)

#define TR_TILE   128
#define TR_TPB    ((NA + TR_TILE - 1) / TR_TILE)   // 69
#define TR_BLOCKS (BATCH * TR_TPB)

// BIT-EXACT equivalent of the reference IoU test (R11 variant, measured best).
__device__ __forceinline__ bool iou_hit(float4 p, float pa, float4 q, float qa) {
    float w = fminf(p.z, q.z) - fmaxf(p.x, q.x) + 1.0f;
    float h = fminf(p.w, q.w) - fmaxf(p.y, q.y) + 1.0f;
    float inter = fmaxf(w, 0.0f) * fmaxf(h, 0.0f);
    float uni = pa + qa - inter;
    return (double)inter > IOU_MID * (double)uni;
}

// identical expression used everywhere areas are produced -> bit-exact
__device__ __forceinline__ float box_area(float4 b) {
    return (b.z - b.x + 1.0f) * (b.w - b.y + 1.0f);
}

__device__ __forceinline__ unsigned finebin(unsigned bits) {
    unsigned fb = (bits - BASEB) >> FSH;
    return fb > (FBINS - 1u) ? (FBINS - 1u) : fb;
}

// Block suffix-scan over FBINS bins (512 threads, 4 consecutive bins each).
__device__ __forceinline__ int suffix_scan_2048(int* hist, int tid, int* sfx,
                                                int* above_out) {
    __shared__ int ws[16];
    __shared__ int s_total;
    const int lane = tid & 31, wid = tid >> 5;
    int b4 = tid * 4;
    int h0 = hist[b4], h1 = hist[b4 + 1], h2 = hist[b4 + 2], h3 = hist[b4 + 3];
    sfx[3] = h3; sfx[2] = h2 + sfx[3]; sfx[1] = h1 + sfx[2]; sfx[0] = h0 + sfx[1];
    int T = sfx[0], S = T;
#pragma unroll
    for (int off = 1; off < 32; off <<= 1) {
        int v = __shfl_down_sync(FULLM, S, off);
        if (lane + off < 32) S += v;
    }
    if (lane == 0) ws[wid] = S;
    __syncthreads();
    if (tid < 16) {
        int W = ws[tid];
#pragma unroll
        for (int off = 1; off < 16; off <<= 1) {
            int v = __shfl_down_sync(0x0000FFFFu, W, off);
            if (tid + off < 16) W += v;
        }
        ws[tid] = W;
        if (tid == 0) s_total = W;
    }
    __syncthreads();
    int above = ((wid < 15) ? ws[wid + 1] : 0) + (S - T);
    sfx[0] += above; sfx[1] += above; sfx[2] += above; sfx[3] += above;
    hist[b4]     = sfx[1];
    hist[b4 + 1] = sfx[2];
    hist[b4 + 2] = sfx[3];
    hist[b4 + 3] = above;
    *above_out = above;
    return s_total;
}

// ============================================================
// Kernel 1: transpose cls [b][a][c] -> g_clsT [b][c][a] (coalesced).
// ============================================================
__global__ void prep_kernel(const float* __restrict__ cls) {
    __shared__ float sh[TR_TILE * NC];
    int t = blockIdx.x;
    int b = t / TR_TPB, tile = t % TR_TPB;
    int a0 = tile * TR_TILE;
    int n = NA - a0; if (n > TR_TILE) n = TR_TILE;
    const float* src = cls + ((size_t)(b * NA + a0)) * NC;
    for (int i = threadIdx.x; i < n * NC; i += 256) sh[i] = src[i];
    __syncthreads();
    int half = threadIdx.x >> 7;
    int t2 = threadIdx.x & 127;
    if (t2 < n) {
        for (int c = half * 10; c < half * 10 + 10; ++c)
            g_clsT[((size_t)(b * NFG + c)) * NAP + a0 + t2] = sh[t2 * NC + c + 1];
    }
}

// ============================================================
// Kernel 2: bucket top-1024 + tile-1 greedy NMS (theta-cut makes
// tiles 2+ provably irrelevant in the common case); last CTA per
// image runs top-200 + theta test + exact cold-path continuation.
// ============================================================
__global__ __launch_bounds__(512, 2) void nms_kernel(const float* __restrict__ loc,
                                                     const float* __restrict__ anch,
                                                     float* __restrict__ out) {
    const int bc  = blockIdx.x;
    const int b   = bc / NFG;
    const int c20 = bc % NFG;
    const int tid = threadIdx.x;

    __shared__ __align__(16) int histbuf[FBINS];             // 8KB
    __shared__ __align__(16) unsigned long long dest[DCAP];  // 10KB
    __shared__ __align__(16) float4 sbox[PRE];               // 16KB
    __shared__ float  sar[PRE], ssc[PRE];                    // 8KB
    __shared__ short  cidx[256];
    __shared__ unsigned kw[8], pf[8];
    __shared__ int psum[8];
    __shared__ int skc[NFG];
    __shared__ int s_fl[2];
    __shared__ int s_ftb, s_sel, s_last, s_ma, s_need;

    int* hist = histbuf;
    unsigned* colmask = (unsigned*)histbuf;
    float4* lbox = (float4*)dest;            // cold path: kept boxes
    float*  lar  = (float*)(dest + 512);     // cold path: kept areas

    for (int i = tid; i < FBINS; i += 512) hist[i] = 0;
    if (tid == 0) { s_ftb = -1; s_sel = 0; }
    __syncthreads();

    const float4* scol4 = reinterpret_cast<const float4*>(
        g_clsT + ((size_t)(b * NFG + c20)) * NAP);

    // ---- A: fine histogram, vectorized float4 (pad scores are 0) ----
    for (int v = tid; v < NAP / 4; v += 512) {
        float4 s4 = scol4[v];
        if (s4.x > CONF_T) atomicAdd(&hist[finebin(__float_as_uint(s4.x))], 1);
        if (s4.y > CONF_T) atomicAdd(&hist[finebin(__float_as_uint(s4.y))], 1);
        if (s4.z > CONF_T) atomicAdd(&hist[finebin(__float_as_uint(s4.z))], 1);
        if (s4.w > CONF_T) atomicAdd(&hist[finebin(__float_as_uint(s4.w))], 1);
    }
    __syncthreads();

    // ---- B: suffix scan; unique-boundary threshold (no atomics) ----
    int sfx[4], above;
    int total = suffix_scan_2048(hist, tid, sfx, &above);
    {
        int need = total < PRE ? total : PRE;
        if (need > 0) {
#pragma unroll
            for (int q = 0; q < 4; ++q) {
                int nxt = (q < 3) ? sfx[q + 1] : above;
                if (sfx[q] >= need && nxt < need) {
                    s_ftb = tid * 4 + q;
                    s_sel = sfx[q];
                }
            }
        }
    }
    __syncthreads();
    const int ftb = s_ftb;
    int count = s_sel; if (count > PRE) count = PRE; if (count > DCAP) count = DCAP;

    // ---- C: scatter to exact positions + per-bin tie sort ----
    if (ftb >= 0) {
        for (int v = tid; v < NAP / 4; v += 512) {
            float4 s4 = scol4[v];
            float sv[4] = {s4.x, s4.y, s4.z, s4.w};
#pragma unroll
            for (int k = 0; k < 4; ++k) {
                if (sv[k] > CONF_T) {
                    unsigned bits = __float_as_uint(sv[k]);
                    int fb = (int)finebin(bits);
                    if (fb >= ftb) {
                        int pos = atomicAdd(&hist[fb], 1);
                        if (pos < DCAP)
                            dest[pos] = ((unsigned long long)bits << 32) |
                                        (unsigned)(65535 - (4 * v + k));
                    }
                }
            }
        }
        __syncthreads();
        for (int fb = ftb + tid; fb < FBINS; fb += 512) {
            int lo = (fb == FBINS - 1) ? 0 : hist[fb + 1];
            int hi = hist[fb];
            if (hi > DCAP) hi = DCAP;
            if (lo > hi) lo = hi;
            for (int x = lo + 1; x < hi; ++x) {
                unsigned long long key = dest[x];
                int y = x - 1;
                while (y >= lo && dest[y] < key) { dest[y + 1] = dest[y]; --y; }
                dest[y + 1] = key;
            }
        }
        __syncthreads();
    }

    // ---- E: decode candidate boxes best-first; spill to global ----
    const float4* loc4  = reinterpret_cast<const float4*>(loc);
    const float4* anch4 = reinterpret_cast<const float4*>(anch);
#pragma unroll
    for (int t = 0; t < 2; ++t) {
        int r = tid + t * 512;
        if (r < count) {
            unsigned long long key = dest[r];
            int a = 65535 - (int)(key & 0xFFFFu);
            float4 l  = loc4[b * NA + a];
            float4 an = anch4[a];
            float cx = an.x + l.x * 0.1f * an.z;
            float cy = an.y + l.y * 0.1f * an.w;
            float w  = an.z * expf(l.z * 0.2f);
            float h  = an.w * expf(l.w * 0.2f);
            float x1 = cx - w * 0.5f;
            float y1 = cy - h * 0.5f;
            float4 bb;
            bb.x = fminf(fmaxf(x1 * 300.0f, 0.0f), 299.0f);
            bb.y = fminf(fmaxf(y1 * 300.0f, 0.0f), 299.0f);
            bb.z = fminf(fmaxf((x1 + w) * 300.0f, 0.0f), 299.0f);
            bb.w = fminf(fmaxf((y1 + h) * 300.0f, 0.0f), 299.0f);
            float sc = __uint_as_float((unsigned)(key >> 32));
            sbox[r] = bb;
            sar[r] = box_area(bb);
            ssc[r] = sc;
            g_cbox[(size_t)bc * PRE + r]   = bb;
            g_cscore[(size_t)bc * PRE + r] = sc;
        }
    }
    if (tid == 0) g_ccount[bc] = count;
    __syncthreads();   // hist & dest dead; colmask overlay live

    // ---- F: tile-1 greedy NMS only (mask + fixpoint) ----
    {
        int m = count < 256 ? count : 256;
        int nL = 0;
        if (m > 0) {
            const int words = (m + 31) >> 5;
#pragma unroll
            for (int q = 0; q < 4; ++q) {
                int jid = tid + q * 512;
                int i = jid & 255, w = jid >> 8;
                int jn = i - w * 32; if (jn > 32) jn = 32;
                if (i < m && w < words) {
                    if (jn > 0) {
                        float4 bi = sbox[i];
                        float ai = sar[i];
                        unsigned bits = 0u;
                        int j0 = w * 32;
                        int l = 0;
                        for (; l + 4 <= jn; l += 4) {
                            if (iou_hit(bi, ai, sbox[j0 + l],     sar[j0 + l]))     bits |= 1u << l;
                            if (iou_hit(bi, ai, sbox[j0 + l + 1], sar[j0 + l + 1])) bits |= 1u << (l + 1);
                            if (iou_hit(bi, ai, sbox[j0 + l + 2], sar[j0 + l + 2])) bits |= 1u << (l + 2);
                            if (iou_hit(bi, ai, sbox[j0 + l + 3], sar[j0 + l + 3])) bits |= 1u << (l + 3);
                        }
                        for (; l < jn; ++l)
                            if (iou_hit(bi, ai, sbox[j0 + l], sar[j0 + l]))
                                bits |= 1u << l;
                        colmask[i * 8 + w] = bits;
                    } else {
                        colmask[i * 8 + w] = 0u;
                    }
                }
            }
            __syncthreads();
            if (tid < 8) {
                int lo = tid * 32;
                unsigned valid;
                if (m >= lo + 32)      valid = FULLM;
                else if (m <= lo)      valid = 0u;
                else                   valid = (1u << (m - lo)) - 1u;
                kw[tid] = valid;
            }
            if (tid == 0) { s_fl[0] = 0; s_fl[1] = 0; }
            unsigned cm[8];
            int pre_ok = (tid < m);
            __syncthreads();
            if (pre_ok) {
#pragma unroll
                for (int w = 0; w < 8; ++w) cm[w] = colmask[tid * 8 + w];
            }
            int p = 0;
            for (;;) {
                int alive = 0;
                if (pre_ok) {
                    unsigned acc = (cm[0] & kw[0]) | (cm[1] & kw[1]) |
                                   (cm[2] & kw[2]) | (cm[3] & kw[3]) |
                                   (cm[4] & kw[4]) | (cm[5] & kw[5]) |
                                   (cm[6] & kw[6]) | (cm[7] & kw[7]);
                    alive = (acc == 0u);
                }
                __syncthreads();
                unsigned nw = __ballot_sync(FULLM, alive);
                if (tid < 256 && (tid & 31) == 0) {
                    if (nw != kw[tid >> 5]) s_fl[p] = 1;
                    kw[tid >> 5] = nw;
                }
                if (tid == 0) s_fl[p ^ 1] = 0;
                __syncthreads();
                if (!s_fl[p]) break;
                p ^= 1;
            }
            if (tid < 8) {
                int s = 0;
                for (int w2 = 0; w2 < tid; ++w2) s += __popc(kw[w2]);
                psum[tid] = s;
            }
            __syncthreads();
            int nk = psum[7] + __popc(kw[7]);
            int take = nk < TOPK ? nk : TOPK;
            if (tid < m && ((kw[tid >> 5] >> (tid & 31)) & 1u)) {
                int r = psum[tid >> 5] + __popc(kw[tid >> 5] & ((1u << (tid & 31)) - 1u));
                if (r < take) {
                    int gb = bc * TOPK + r;
                    g_kscore[gb] = ssc[tid];
                    g_kbox[gb]   = sbox[tid];
                }
            }
            nL = take;
        }
        if (tid == 0) g_kcount[bc] = nL;
    }

    // ---- G: completion counter; last CTA of image finalizes ----
    if (tid == 0) {
        __threadfence();
        unsigned old = atomicInc(&g_done[b], NFG - 1);
        s_last = (old == NFG - 1);
    }
    __syncthreads();
    if (!s_last) return;
    __threadfence();

    // ---- H: finalize. pass0: top-200 + theta; cold continuation; pass1 redo.
    int count2 = 0;
    for (int pass = 0; pass < 2; ++pass) {
        for (int i = tid; i < FBINS; i += 512) hist[i] = 0;
        if (tid == 0) { s_ftb = -1; s_sel = 0; }
        if (tid < NFG) skc[tid] = g_kcount[b * NFG + tid];
        __syncthreads();

        for (int idx = tid; idx < NFG * TOPK; idx += 512) {
            int c = idx / TOPK, slot = idx - c * TOPK;
            if (slot < skc[c]) {
                unsigned bits = __float_as_uint(g_kscore[(b * NFG + c) * TOPK + slot]);
                atomicAdd(&hist[finebin(bits)], 1);
            }
        }
        __syncthreads();

        int total2 = suffix_scan_2048(hist, tid, sfx, &above);
        {
            int need = total2 < TOPK ? total2 : TOPK;
            if (need > 0) {
#pragma unroll
                for (int q = 0; q < 4; ++q) {
                    int nxt = (q < 3) ? sfx[q + 1] : above;
                    if (sfx[q] >= need && nxt < need) {
                        s_ftb = tid * 4 + q;
                        s_sel = sfx[q];
                    }
                }
            }
        }
        __syncthreads();
        const int ftb2 = s_ftb;
        count2 = s_sel; if (count2 > TOPK) count2 = TOPK; if (count2 > 512) count2 = 512;

        if (ftb2 >= 0) {
            for (int idx = tid; idx < NFG * TOPK; idx += 512) {
                int c = idx / TOPK, slot = idx - c * TOPK;
                if (slot < skc[c]) {
                    unsigned bits = __float_as_uint(g_kscore[(b * NFG + c) * TOPK + slot]);
                    int fb = (int)finebin(bits);
                    if (fb >= ftb2) {
                        int pos = atomicAdd(&hist[fb], 1);
                        if (pos < 512)
                            dest[pos] = ((unsigned long long)bits << 32) |
                                        (0xFFFFFFFFu - (unsigned)(c * 256 + slot));
                    }
                }
            }
            __syncthreads();
            for (int fb = ftb2 + tid; fb < FBINS; fb += 512) {
                int lo = (fb == FBINS - 1) ? 0 : hist[fb + 1];
                int hi = hist[fb];
                if (hi > 512) hi = 512;
                if (lo > hi) lo = hi;
                for (int x = lo + 1; x < hi; ++x) {
                    unsigned long long key = dest[x];
                    int y = x - 1;
                    while (y >= lo && dest[y] < key) { dest[y + 1] = dest[y]; --y; }
                    dest[y + 1] = key;
                }
            }
            __syncthreads();
        }
        if (pass == 1) break;

        // theta-cut test: class needs continuation iff kept<200, candidates
        // remain past 256, and next score could still reach global top-200.
        unsigned thetab = (count2 >= TOPK) ? (unsigned)(dest[TOPK - 1] >> 32) : 0u;
        if (tid < 32) {
            int needc = 0;
            if (tid < NFG) {
                int kc = skc[tid];
                int cc = g_ccount[b * NFG + tid];
                if (kc < TOPK && cc > 256) {
                    unsigned nb = __float_as_uint(
                        g_cscore[((size_t)(b * NFG + tid)) * PRE + 256]);
                    if (count2 < TOPK || nb >= thetab) needc = 1;
                }
            }
            unsigned bal = __ballot_sync(FULLM, needc);
            if (tid == 0) s_need = (int)bal;
        }
        __syncthreads();
        if (!s_need) break;                    // fast path: done

        // ---- cold path: exact continuation (tiles 2+) per needed class ----
        for (int c = 0; c < NFG; ++c) {
            if (!((s_need >> c) & 1)) continue;
            int bcc = b * NFG + c;
            int cc = g_ccount[bcc]; if (cc > PRE) cc = PRE;
            int nL = skc[c];
            for (int i = tid; i < nL; i += 512) {
                float4 kb = g_kbox[bcc * TOPK + i];
                lbox[i] = kb;
                lar[i]  = box_area(kb);
            }
            __syncthreads();
            for (int base = 256; base < cc && nL < TOPK; base += 256) {
                int m = cc - base; if (m > 256) m = 256;
                if (tid < m) {
                    float4 bb = g_cbox[(size_t)bcc * PRE + base + tid];
                    sbox[tid] = bb;
                    sar[tid]  = box_area(bb);
                    ssc[tid]  = g_cscore[(size_t)bcc * PRE + base + tid];
                }
                if (tid < 8) pf[tid] = 0u;
                __syncthreads();
                if (nL > 0) {
                    int i = tid >> 1, half = tid & 1;
                    if (i < m) {
                        float4 bb = sbox[i];
                        float ab = sar[i];
                        bool dead = false;
                        for (int k = half; k < nL; k += 2)
                            dead |= iou_hit(lbox[k], lar[k], bb, ab);
                        if (dead) atomicOr(&pf[i >> 5], 1u << (i & 31));
                    }
                }
                __syncthreads();
                if (tid < 8) {
                    int lo = tid * 32;
                    unsigned valid;
                    if (m >= lo + 32)      valid = FULLM;
                    else if (m <= lo)      valid = 0u;
                    else                   valid = (1u << (m - lo)) - 1u;
                    pf[tid] = valid & ~pf[tid];
                }
                __syncthreads();
                if (tid < 8) {
                    int s = 0;
                    for (int w2 = 0; w2 < tid; ++w2) s += __popc(pf[w2]);
                    psum[tid] = s;
                    if (tid == 7) s_ma = s + __popc(pf[7]);
                }
                __syncthreads();
                const int ma = s_ma;
                if (ma > 0) {
                    if (tid < m && ((pf[tid >> 5] >> (tid & 31)) & 1u)) {
                        int r = psum[tid >> 5] +
                                __popc(pf[tid >> 5] & ((1u << (tid & 31)) - 1u));
                        cidx[r] = (short)tid;
                    }
                    __syncthreads();
                    const int words = (ma + 31) >> 5;
#pragma unroll
                    for (int q = 0; q < 4; ++q) {
                        int jid = tid + q * 512;
                        int i = jid & 255, w = jid >> 8;
                        int jn = i - w * 32; if (jn > 32) jn = 32;
                        if (i < ma && w < words) {
                            if (jn > 0) {
                                float4 bi = sbox[cidx[i]];
                                float ai = sar[cidx[i]];
                                unsigned bits = 0u;
                                int j0 = w * 32;
                                for (int l = 0; l < jn; ++l) {
                                    int aj = cidx[j0 + l];
                                    if (iou_hit(bi, ai, sbox[aj], sar[aj]))
                                        bits |= 1u << l;
                                }
                                colmask[i * 8 + w] = bits;
                            } else {
                                colmask[i * 8 + w] = 0u;
                            }
                        }
                    }
                    __syncthreads();
                    if (tid < 8) {
                        int lo = tid * 32;
                        unsigned valid;
                        if (ma >= lo + 32)      valid = FULLM;
                        else if (ma <= lo)      valid = 0u;
                        else                    valid = (1u << (ma - lo)) - 1u;
                        kw[tid] = valid;
                    }
                    if (tid == 0) { s_fl[0] = 0; s_fl[1] = 0; }
                    unsigned cm[8];
                    int pre_ok = (tid < ma);
                    __syncthreads();
                    if (pre_ok) {
#pragma unroll
                        for (int w = 0; w < 8; ++w) cm[w] = colmask[tid * 8 + w];
                    }
                    int p = 0;
                    for (;;) {
                        int alive = 0;
                        if (pre_ok) {
                            unsigned acc = (cm[0] & kw[0]) | (cm[1] & kw[1]) |
                                           (cm[2] & kw[2]) | (cm[3] & kw[3]) |
                                           (cm[4] & kw[4]) | (cm[5] & kw[5]) |
                                           (cm[6] & kw[6]) | (cm[7] & kw[7]);
                            alive = (acc == 0u);
                        }
                        __syncthreads();
                        unsigned nw = __ballot_sync(FULLM, alive);
                        if (tid < 256 && (tid & 31) == 0) {
                            if (nw != kw[tid >> 5]) s_fl[p] = 1;
                            kw[tid >> 5] = nw;
                        }
                        if (tid == 0) s_fl[p ^ 1] = 0;
                        __syncthreads();
                        if (!s_fl[p]) break;
                        p ^= 1;
                    }
                    if (tid < 8) {
                        int s = 0;
                        for (int w2 = 0; w2 < tid; ++w2) s += __popc(kw[w2]);
                        psum[tid] = s;
                    }
                    __syncthreads();
                    int nk = psum[7] + __popc(kw[7]);
                    int take = TOPK - nL; if (take > nk) take = nk;
                    if (tid < ma && ((kw[tid >> 5] >> (tid & 31)) & 1u)) {
                        int r = psum[tid >> 5] +
                                __popc(kw[tid >> 5] & ((1u << (tid & 31)) - 1u));
                        if (r < take) {
                            int slot = nL + r;
                            int src = cidx[tid];
                            g_kscore[bcc * TOPK + slot] = ssc[src];
                            g_kbox[bcc * TOPK + slot]   = sbox[src];
                            lbox[slot] = sbox[src];
                            lar[slot]  = sar[src];
                        }
                    }
                    nL += take;
                }
                __syncthreads();
            }
            if (tid == 0) g_kcount[bcc] = nL;
            __syncthreads();
        }
        __syncthreads();
    }

    // ---- output from dest ----
    if (tid < TOPK) {
        float b0 = 0.f, b1 = 0.f, b2 = 0.f, b3 = 0.f, sco = 0.f, lab = 0.f;
        if (tid < count2) {
            unsigned long long key = dest[tid];
            unsigned code = 0xFFFFFFFFu - (unsigned)(key & 0xFFFFFFFFu);
            int c    = (int)(code >> 8);
            int slot = (int)(code & 255u);
            float4 kb = g_kbox[(b * NFG + c) * TOPK + slot];
            sco = __uint_as_float((unsigned)(key >> 32));
            b0 = kb.x; b1 = kb.y; b2 = kb.z; b3 = kb.w;
            lab = (float)(c + 1);
        }
        out[(b * TOPK + tid) * 4 + 0] = b0;
        out[(b * TOPK + tid) * 4 + 1] = b1;
        out[(b * TOPK + tid) * 4 + 2] = b2;
        out[(b * TOPK + tid) * 4 + 3] = b3;
        out[BATCH * TOPK * 4 + b * TOPK + tid] = sco;
        out[BATCH * TOPK * 5 + b * TOPK + tid] = lab;
    }
}

// ============================================================
extern "C" void kernel_launch(void* const* d_in, const int* in_sizes, int n_in,
                              void* d_out, int out_size) {
    const float* cls  = (const float*)d_in[0];  // [8, 8732, 21]
    const float* loc  = (const float*)d_in[1];  // [8, 8732, 4]
    const float* anch = (const float*)d_in[2];  // [8732, 4]
    float* out = (float*)d_out;

    prep_kernel<<<TR_BLOCKS, 256>>>(cls);
    nms_kernel<<<BATCH * NFG, 512>>>(loc, anch, out);
}